// round 15
// baseline (speedup 1.0000x reference)
#include <cuda_runtime.h>
#include <cuda_bf16.h>

// Problem constants (match reference_code)
#define N_L   90
#define N_B   20
#define N_MU  46
#define N_LF  51
#define N_OUTK (N_LF - N_MU + 1)          // 6
#define NBINS (N_L * N_B * N_MU)          // 82800
#define N_LB  (N_L * N_B)                 // 1800
#define NOUT  (N_LB * N_OUTK)             // 10800

#define MN0  (-90.0f)
#define MN1  (-12.0f)
#define MN2  (7.0f)

#define THREADS        256
#define PER_THREAD     8
#define PART_PER_BLOCK (THREADS * PER_THREAD)   // 2048
#define HALF_PART      (PART_PER_BLOCK / 2)     // 1024

#define WARPS_PER_CONV_BLOCK 8
#define CONV_BLOCKS ((N_LB + WARPS_PER_CONV_BLOCK - 1) / WARPS_PER_CONV_BLOCK) // 225

// Zero-initialized at module load; re-zeroed by conv_zero_kernel (each block
// zeroes exactly the bin region its warps consumed). Deterministic per replay.
static __device__ float g_hist[NBINS];

__device__ __forceinline__ int bin_of(float x, float y, float z,
                                      float idx0, float idx1, float idx2) {
    int i0 = __float2int_rn((x - MN0) * idx0);
    int i1 = __float2int_rn((y - MN1) * idx1);
    int i2 = __float2int_rn((z - MN2) * idx2);
    bool ok = (unsigned)i0 < (unsigned)N_L &&
              (unsigned)i1 < (unsigned)N_B &&
              (unsigned)i2 < (unsigned)N_MU;
    return ok ? (i0 * (N_B * N_MU) + i1 * N_MU + i2) : -1;
}

__device__ __forceinline__ void red_add(int b, float m) {
    if (b >= 0) {
        // No-return global reduction (REDG), not ATOMG. Fire-and-forget:
        // blocks retire while REDs drain (critical — do NOT fence).
        asm volatile("red.global.add.f32 [%0], %1;"
                     :: "l"(&g_hist[b]), "f"(m) : "memory");
    }
}

// ======== hist kernel: byte-identical to the R14 measured best (~132.8us) ========
__global__ void __launch_bounds__(THREADS)
hist_kernel(const float* __restrict__ lbm,
            const float* __restrict__ mass,
            int n) {
    __shared__ float sc[PART_PER_BLOCK * 3];   // 24 KB coords
    __shared__ float sm[PART_PER_BLOCK];       //  8 KB masses

    const float dx0 = (90.0f - (-90.0f)) / (float)(N_L - 1);
    const float dx1 = (12.0f - (-12.0f)) / (float)(N_B - 1);
    const float dx2 = (16.0f - 7.0f) / (float)(N_MU - 1);
    const float idx0 = 1.0f / dx0;
    const float idx1 = 1.0f / dx1;
    const float idx2 = 1.0f / dx2;

    const int t   = threadIdx.x;
    const int bs  = blockIdx.x * PART_PER_BLOCK;        // block start particle
    const int cnt = min(PART_PER_BLOCK, n - bs);

    if (cnt == PART_PER_BLOCK) {
        const float4* c4 = (const float4*)(lbm + (size_t)bs * 3);
        float4* s4 = (float4*)sc;
#pragma unroll
        for (int i = 0; i < 6; i++) s4[t + THREADS * i] = c4[t + THREADS * i];
        const float4* m4 = (const float4*)(mass + bs);
        float4* sm4 = (float4*)sm;
        sm4[t + THREADS * 0] = m4[t + THREADS * 0];
        sm4[t + THREADS * 1] = m4[t + THREADS * 1];
    } else {
        for (int i = t; i < cnt * 3; i += THREADS) sc[i] = lbm[(size_t)bs * 3 + i];
        for (int i = t; i < cnt;     i += THREADS) sm[i] = mass[bs + i];
    }
    __syncthreads();

    if (cnt == PART_PER_BLOCK) {
#pragma unroll
        for (int half = 0; half < 2; half++) {
            const int p0 = 4 * t + half * HALF_PART;   // 4 consecutive particles
            float4 a = *(const float4*)&sc[3 * p0 + 0];
            float4 b = *(const float4*)&sc[3 * p0 + 4];
            float4 c = *(const float4*)&sc[3 * p0 + 8];
            float4 m = *(const float4*)&sm[p0];

            int b0 = bin_of(a.x, a.y, a.z, idx0, idx1, idx2);
            int b1 = bin_of(a.w, b.x, b.y, idx0, idx1, idx2);
            int b2 = bin_of(b.z, b.w, c.x, idx0, idx1, idx2);
            int b3 = bin_of(c.y, c.z, c.w, idx0, idx1, idx2);
            red_add(b0, m.x);
            red_add(b1, m.y);
            red_add(b2, m.z);
            red_add(b3, m.w);
        }
    } else {
#pragma unroll
        for (int j = 0; j < PER_THREAD; j++) {
            int p = t + THREADS * j;
            if (p < cnt) {
                int bb = bin_of(sc[3 * p + 0], sc[3 * p + 1], sc[3 * p + 2],
                                idx0, idx1, idx2);
                red_add(bb, sm[p]);
            }
        }
    }
}

// ======== conv+zero: one WARP per (l,b); pre-work hoisted above the PDL sync ========
__global__ void __launch_bounds__(THREADS)
conv_zero_kernel(const float* __restrict__ lf, float* __restrict__ out) {
    __shared__ float s_lf[N_LF];
    const int t    = threadIdx.x;
    const int lane = t & 31;
    const int w    = t >> 5;
    const int lb   = blockIdx.x * WARPS_PER_CONV_BLOCK + w;

    // ---- pre-work that does NOT depend on hist: overlaps hist's drain ----
    if (t < N_LF) s_lf[t] = lf[t];
    __syncthreads();

    float lfa[N_OUTK], lfb[N_OUTK];
#pragma unroll
    for (int k = 0; k < N_OUTK; k++) {
        lfa[k] = s_lf[k + (N_MU - 1) - lane];
        lfb[k] = (lane < N_MU - 32) ? s_lf[k + (N_MU - 1) - 32 - lane] : 0.0f;
    }
    float* h = &g_hist[lb * N_MU];

    // ---- dependency point: wait for hist completion ----
    cudaGridDependencySynchronize();

    if (lb < N_LB) {
        const float v0 = __ldcg(&h[lane]);
        const float v1 = (lane < N_MU - 32) ? __ldcg(&h[lane + 32]) : 0.0f;

        float p[N_OUTK];
#pragma unroll
        for (int k = 0; k < N_OUTK; k++) {
            p[k] = fmaf(v0, lfa[k], v1 * lfb[k]);
        }
#pragma unroll
        for (int off = 16; off > 0; off >>= 1) {
#pragma unroll
            for (int k = 0; k < N_OUTK; k++) {
                p[k] += __shfl_xor_sync(0xFFFFFFFFu, p[k], off);
            }
        }
        if (lane < N_OUTK) out[lb * N_OUTK + lane] = p[lane];
    }

    // ---- block-level zeroing: 8 slices = 368 floats = 92 float4, 16B aligned ----
    __syncthreads();   // all warps finished reading their slices
    {
        const int base_f = blockIdx.x * WARPS_PER_CONV_BLOCK * N_MU;
        const int nf = min(WARPS_PER_CONV_BLOCK * N_MU, NBINS - base_f);
        if (nf > 0) {
            float4* z4 = (float4*)&g_hist[base_f];
            const int n4 = nf / 4;                        // 368 % 4 == 0
            for (int i = t; i < n4; i += THREADS) {
                z4[i] = make_float4(0.f, 0.f, 0.f, 0.f);
            }
        }
    }
}

extern "C" void kernel_launch(void* const* d_in, const int* in_sizes, int n_in,
                              void* d_out, int out_size) {
    const float* lbm  = (const float*)d_in[0];   // [N,3] float32
    const float* mass = (const float*)d_in[1];   // [N]   float32
    const float* lf   = (const float*)d_in[2];   // [51]  float32
    float* out = (float*)d_out;                  // [90,20,6] float32

    int n = in_sizes[1];
    int grid = (n + PART_PER_BLOCK - 1) / PART_PER_BLOCK;
    if (grid < 1) grid = 1;

    hist_kernel<<<grid, THREADS>>>(lbm, mass, n);

    // PDL launch: conv_zero prelaunches and runs its lf/index pre-work while
    // hist drains; only the hist reads sit behind the dependency sync.
    {
        cudaLaunchConfig_t cfg = {};
        cfg.gridDim  = dim3(CONV_BLOCKS, 1, 1);
        cfg.blockDim = dim3(THREADS, 1, 1);
        cfg.dynamicSmemBytes = 0;
        cfg.stream = 0;
        cudaLaunchAttribute attrs[1];
        attrs[0].id = cudaLaunchAttributeProgrammaticStreamSerialization;
        attrs[0].val.programmaticStreamSerializationAllowed = 1;
        cfg.attrs = attrs;
        cfg.numAttrs = 1;
        cudaLaunchKernelEx(&cfg, conv_zero_kernel, lf, out);
    }
}

// round 16
// speedup vs baseline: 1.0049x; 1.0049x over previous
#include <cuda_runtime.h>
#include <cuda_bf16.h>

// Problem constants (match reference_code)
#define N_L   90
#define N_B   20
#define N_MU  46
#define N_LF  51
#define N_OUTK (N_LF - N_MU + 1)          // 6
#define NBINS (N_L * N_B * N_MU)          // 82800
#define N_LB  (N_L * N_B)                 // 1800
#define NOUT  (N_LB * N_OUTK)             // 10800

#define MN0  (-90.0f)
#define MN1  (-12.0f)
#define MN2  (7.0f)

#define THREADS        256
#define PER_THREAD     8
#define PART_PER_BLOCK (THREADS * PER_THREAD)   // 2048
#define HALF_PART      (PART_PER_BLOCK / 2)     // 1024

#define CONV_THREADS   128
#define WARPS_PER_CONV_BLOCK (CONV_THREADS / 32)   // 4
#define CONV_BLOCKS ((N_LB + WARPS_PER_CONV_BLOCK - 1) / WARPS_PER_CONV_BLOCK) // 450

// Zero-initialized at module load; re-zeroed by conv_zero_kernel (each warp
// zeroes exactly the 46-bin slice it alone consumed). Deterministic per replay.
static __device__ float g_hist[NBINS];

__device__ __forceinline__ int bin_of(float x, float y, float z,
                                      float idx0, float idx1, float idx2) {
    int i0 = __float2int_rn((x - MN0) * idx0);
    int i1 = __float2int_rn((y - MN1) * idx1);
    int i2 = __float2int_rn((z - MN2) * idx2);
    bool ok = (unsigned)i0 < (unsigned)N_L &&
              (unsigned)i1 < (unsigned)N_B &&
              (unsigned)i2 < (unsigned)N_MU;
    return ok ? (i0 * (N_B * N_MU) + i1 * N_MU + i2) : -1;
}

__device__ __forceinline__ void red_add(int b, float m) {
    if (b >= 0) {
        // No-return global reduction (REDG), not ATOMG. Fire-and-forget:
        // blocks retire while REDs drain (critical — do NOT fence).
        asm volatile("red.global.add.f32 [%0], %1;"
                     :: "l"(&g_hist[b]), "f"(m) : "memory");
    }
}

// ======== hist kernel: byte-identical to the R14 measured best (~132.8us) ========
__global__ void __launch_bounds__(THREADS)
hist_kernel(const float* __restrict__ lbm,
            const float* __restrict__ mass,
            int n) {
    __shared__ float sc[PART_PER_BLOCK * 3];   // 24 KB coords
    __shared__ float sm[PART_PER_BLOCK];       //  8 KB masses

    const float dx0 = (90.0f - (-90.0f)) / (float)(N_L - 1);
    const float dx1 = (12.0f - (-12.0f)) / (float)(N_B - 1);
    const float dx2 = (16.0f - 7.0f) / (float)(N_MU - 1);
    const float idx0 = 1.0f / dx0;
    const float idx1 = 1.0f / dx1;
    const float idx2 = 1.0f / dx2;

    const int t   = threadIdx.x;
    const int bs  = blockIdx.x * PART_PER_BLOCK;        // block start particle
    const int cnt = min(PART_PER_BLOCK, n - bs);

    if (cnt == PART_PER_BLOCK) {
        const float4* c4 = (const float4*)(lbm + (size_t)bs * 3);
        float4* s4 = (float4*)sc;
#pragma unroll
        for (int i = 0; i < 6; i++) s4[t + THREADS * i] = c4[t + THREADS * i];
        const float4* m4 = (const float4*)(mass + bs);
        float4* sm4 = (float4*)sm;
        sm4[t + THREADS * 0] = m4[t + THREADS * 0];
        sm4[t + THREADS * 1] = m4[t + THREADS * 1];
    } else {
        for (int i = t; i < cnt * 3; i += THREADS) sc[i] = lbm[(size_t)bs * 3 + i];
        for (int i = t; i < cnt;     i += THREADS) sm[i] = mass[bs + i];
    }
    __syncthreads();

    if (cnt == PART_PER_BLOCK) {
#pragma unroll
        for (int half = 0; half < 2; half++) {
            const int p0 = 4 * t + half * HALF_PART;   // 4 consecutive particles
            float4 a = *(const float4*)&sc[3 * p0 + 0];
            float4 b = *(const float4*)&sc[3 * p0 + 4];
            float4 c = *(const float4*)&sc[3 * p0 + 8];
            float4 m = *(const float4*)&sm[p0];

            int b0 = bin_of(a.x, a.y, a.z, idx0, idx1, idx2);
            int b1 = bin_of(a.w, b.x, b.y, idx0, idx1, idx2);
            int b2 = bin_of(b.z, b.w, c.x, idx0, idx1, idx2);
            int b3 = bin_of(c.y, c.z, c.w, idx0, idx1, idx2);
            red_add(b0, m.x);
            red_add(b1, m.y);
            red_add(b2, m.z);
            red_add(b3, m.w);
        }
    } else {
#pragma unroll
        for (int j = 0; j < PER_THREAD; j++) {
            int p = t + THREADS * j;
            if (p < cnt) {
                int bb = bin_of(sc[3 * p + 0], sc[3 * p + 1], sc[3 * p + 2],
                                idx0, idx1, idx2);
                red_add(bb, sm[p]);
            }
        }
    }
}

// ======== conv+zero: one WARP per (l,b), no smem, no __syncthreads ========
// Lanes read lf directly (__ldg, L2-hit) — removes block-wide syncs from the
// critical path; each warp proceeds and zeroes its own slice independently.
__global__ void __launch_bounds__(CONV_THREADS)
conv_zero_kernel(const float* __restrict__ lf, float* __restrict__ out) {
    const int t    = threadIdx.x;
    const int lane = t & 31;
    const int lb   = blockIdx.x * WARPS_PER_CONV_BLOCK + (t >> 5);

    // Pre-work independent of hist (overlaps the PDL window).
    float lfa[N_OUTK], lfb[N_OUTK];
#pragma unroll
    for (int k = 0; k < N_OUTK; k++) {
        lfa[k] = __ldg(&lf[k + (N_MU - 1) - lane]);
        lfb[k] = (lane < N_MU - 32) ? __ldg(&lf[k + (N_MU - 1) - 32 - lane]) : 0.0f;
    }
    float* h = &g_hist[lb * N_MU];

    // Dependency point: hist writes visible after this.
    cudaGridDependencySynchronize();

    if (lb >= N_LB) return;

    const float v0 = __ldcg(&h[lane]);                              // lanes 0..31
    const float v1 = (lane < N_MU - 32) ? __ldcg(&h[lane + 32]) : 0.0f; // 0..13

    float p[N_OUTK];
#pragma unroll
    for (int k = 0; k < N_OUTK; k++) {
        p[k] = fmaf(v0, lfa[k], v1 * lfb[k]);
    }
#pragma unroll
    for (int off = 16; off > 0; off >>= 1) {
#pragma unroll
        for (int k = 0; k < N_OUTK; k++) {
            p[k] += __shfl_xor_sync(0xFFFFFFFFu, p[k], off);
        }
    }
    if (lane < N_OUTK) out[lb * N_OUTK + lane] = p[lane];

    // Zero the slice this warp alone read (no sync needed).
    h[lane] = 0.0f;
    if (lane < N_MU - 32) h[lane + 32] = 0.0f;
}

extern "C" void kernel_launch(void* const* d_in, const int* in_sizes, int n_in,
                              void* d_out, int out_size) {
    const float* lbm  = (const float*)d_in[0];   // [N,3] float32
    const float* mass = (const float*)d_in[1];   // [N]   float32
    const float* lf   = (const float*)d_in[2];   // [51]  float32
    float* out = (float*)d_out;                  // [90,20,6] float32

    int n = in_sizes[1];
    int grid = (n + PART_PER_BLOCK - 1) / PART_PER_BLOCK;
    if (grid < 1) grid = 1;

    hist_kernel<<<grid, THREADS>>>(lbm, mass, n);

    // PDL launch: conv_zero prelaunches while hist drains.
    {
        cudaLaunchConfig_t cfg = {};
        cfg.gridDim  = dim3(CONV_BLOCKS, 1, 1);
        cfg.blockDim = dim3(CONV_THREADS, 1, 1);
        cfg.dynamicSmemBytes = 0;
        cfg.stream = 0;
        cudaLaunchAttribute attrs[1];
        attrs[0].id = cudaLaunchAttributeProgrammaticStreamSerialization;
        attrs[0].val.programmaticStreamSerializationAllowed = 1;
        cfg.attrs = attrs;
        cfg.numAttrs = 1;
        cudaLaunchKernelEx(&cfg, conv_zero_kernel, lf, out);
    }
}